// round 14
// baseline (speedup 1.0000x reference)
#include <cuda_runtime.h>
#include <cstdint>

#define N_VOX   262144
#define M_PAIRS 131072
#define K_OFF   27
#define C       32
#define CPAD    36        // row stride in floats (144B; halves' chunks bank-disjoint)

// ---------------------------------------------------------------------------
// Kernel 1: out[n][c] = bias[c]  (bias add commutes with the scatter-adds)
// ---------------------------------------------------------------------------
__global__ void bias_init_kernel(float* __restrict__ out,
                                 const float* __restrict__ bias)
{
    int t = blockIdx.x * blockDim.x + threadIdx.x;
    const int total4 = N_VOX * (C / 4);
    if (t < total4) {
        const float4* b4 = (const float4*)bias;
        float4* o4 = (float4*)out;
        o4[t] = b4[t & 7];
    }
}

// ---------------------------------------------------------------------------
// Kernel 2: multi-tile block, double-buffered TMA bulk gather -> smem ->
//           input-packed f32x2 GEMM -> red.v2 scatter.
//   R13 structure with register-pressure fixes: occupancy cap (5 blocks/SM),
//   unroll-1 tile loop, incrementing map pointers.
// ---------------------------------------------------------------------------
#define THREADS          128
#define WARPS_PER_BLOCK  4
#define PAIRS_PER_BLOCK  128
#define PAIRS_PER_WARP   32
#define STEPS            16            // 2 pairs per step (one per half-warp)
#define TILES            8             // tiles (of 128 pairs) per block

__device__ __forceinline__ uint32_t smem_u32(const void* p) {
    uint32_t a;
    asm("{ .reg .u64 t; cvta.to.shared.u64 t, %1; cvt.u32.u64 %0, t; }"
        : "=r"(a) : "l"(p));
    return a;
}

__device__ __forceinline__ void mbar_wait(uint32_t mbar_a, uint32_t parity) {
    uint32_t done;
    asm volatile(
        "{\n\t"
        ".reg .pred p;\n\t"
        "mbarrier.try_wait.parity.acquire.cta.shared::cta.b64 p, [%1], %2;\n\t"
        "selp.b32 %0, 1, 0, p;\n\t"
        "}"
        : "=r"(done) : "r"(mbar_a), "r"(parity) : "memory");
    if (!done) {
        asm volatile(
            "{\n\t"
            ".reg .pred P1;\n\t"
            "WAIT_LOOP_%=:\n\t"
            "mbarrier.try_wait.parity.acquire.cta.shared::cta.b64 P1, [%0], %1, 0x989680;\n\t"
            "@P1 bra.uni WAIT_DONE_%=;\n\t"
            "bra.uni WAIT_LOOP_%=;\n\t"
            "WAIT_DONE_%=:\n\t"
            "}"
            :: "r"(mbar_a), "r"(parity) : "memory");
    }
}

__global__ __launch_bounds__(THREADS, 5)
void scatter_gemm_kernel(const float* __restrict__ input,
                         const float* __restrict__ kernel,
                         const int*   __restrict__ in_map,
                         const int*   __restrict__ out_map,
                         float*       __restrict__ out)
{
    __shared__ float srow[2][PAIRS_PER_BLOCK][CPAD];   // 36 KB ring of rows
    __shared__ alignas(8) unsigned long long mbar[2];

    const int k     = blockIdx.y;
    const int lane  = threadIdx.x & 31;
    const int warp  = threadIdx.x >> 5;
    const int half  = lane >> 4;          // which pair of the step
    const int chalf = lane & 15;          // covers channels 2*chalf, 2*chalf+1

    const int base0 = blockIdx.x * (PAIRS_PER_BLOCK * TILES);
    // Incrementing map pointers (kept minimal; advanced per tile).
    const int* im_next = in_map  + k * M_PAIRS + base0 + threadIdx.x;  // gather row for THIS thread
    const int* om_tile = out_map + k * M_PAIRS + base0;                // tile base for scatter

    const uint32_t mbar_a0 = smem_u32(&mbar[0]);
    const uint32_t mbar_a1 = smem_u32(&mbar[1]);

    if (threadIdx.x == 0) {
        asm volatile("mbarrier.init.shared.b64 [%0], 1;" :: "r"(mbar_a0) : "memory");
        asm volatile("mbarrier.init.shared.b64 [%0], 1;" :: "r"(mbar_a1) : "memory");
    }
    __syncthreads();

    const uint32_t my_dst0 = smem_u32(&srow[0][threadIdx.x][0]);
    const uint32_t my_dst1 = smem_u32(&srow[1][threadIdx.x][0]);

    // ---- Prologue: issue gather for tile 0 into buffer 0.
    {
        if (threadIdx.x == 0)
            asm volatile("mbarrier.arrive.expect_tx.shared.b64 _, [%0], %1;"
                         :: "r"(mbar_a0), "r"(PAIRS_PER_BLOCK * C * 4) : "memory");
        const int irow = __ldg(im_next);
        im_next += PAIRS_PER_BLOCK;
        const float* src = input + (size_t)irow * C;
        asm volatile(
            "cp.async.bulk.shared::cta.global.mbarrier::complete_tx::bytes "
            "[%0], [%1], %2, [%3];"
            :: "r"(my_dst0), "l"(src), "r"(C * 4), "r"(mbar_a0) : "memory");
    }

    // ---- Weights (once per block; overlap with tile-0 gather):
    //   wA[i] = (W[2i][c0], W[2i+1][c0]),  wB[i] = (W[2i][c1], W[2i+1][c1])
    const float* Wk = kernel + k * C * C;
    unsigned long long wA[C / 2], wB[C / 2];
    #pragma unroll
    for (int i = 0; i < C / 2; i++) {
        float2 f = __ldg((const float2*)(Wk + (2 * i)     * C) + chalf);
        float2 g = __ldg((const float2*)(Wk + (2 * i + 1) * C) + chalf);
        asm("mov.b64 %0, {%1, %2};" : "=l"(wA[i]) : "f"(f.x), "f"(g.x));
        asm("mov.b64 %0, {%1, %2};" : "=l"(wB[i]) : "f"(f.y), "f"(g.y));
    }

    const int pbase = warp * PAIRS_PER_WARP;

    #pragma unroll 1
    for (int t = 0; t < TILES; t++) {
        const int buf = t & 1;

        // ---- Issue gather for tile t+1 into the other buffer.
        if (t + 1 < TILES) {
            const uint32_t nmb  = (t & 1) ? mbar_a0 : mbar_a1;
            const uint32_t ndst = (t & 1) ? my_dst0 : my_dst1;
            if (threadIdx.x == 0)
                asm volatile("mbarrier.arrive.expect_tx.shared.b64 _, [%0], %1;"
                             :: "r"(nmb), "r"(PAIRS_PER_BLOCK * C * 4) : "memory");
            const int irow = __ldg(im_next);
            im_next += PAIRS_PER_BLOCK;
            const float* src = input + (size_t)irow * C;
            asm volatile(
                "cp.async.bulk.shared::cta.global.mbarrier::complete_tx::bytes "
                "[%0], [%1], %2, [%3];"
                :: "r"(ndst), "l"(src), "r"(C * 4), "r"(nmb) : "memory");
        }

        // ---- Wait for tile t's rows (buffer buf, use index t>>1).
        mbar_wait(buf ? mbar_a1 : mbar_a0, (t >> 1) & 1);

        // ---- Compute + scatter.
        const int* om_w = om_tile + pbase;
        #pragma unroll 4
        for (int s = 0; s < STEPS; s++) {
            const int pw   = 2 * s + half;
            const int orow = __ldg(om_w + pw);

            const ulonglong2* r2 = (const ulonglong2*)&srow[buf][pbase + pw][0];

            unsigned long long accA = 0ULL, accB = 0ULL;
            #pragma unroll
            for (int j = 0; j < C / 4; j++) {
                ulonglong2 a = r2[j];           // LDS.128, 2 distinct rows/warp
                asm("fma.rn.f32x2 %0, %1, %2, %0;" : "+l"(accA) : "l"(a.x), "l"(wA[2 * j]));
                asm("fma.rn.f32x2 %0, %1, %2, %0;" : "+l"(accA) : "l"(a.y), "l"(wA[2 * j + 1]));
                asm("fma.rn.f32x2 %0, %1, %2, %0;" : "+l"(accB) : "l"(a.x), "l"(wB[2 * j]));
                asm("fma.rn.f32x2 %0, %1, %2, %0;" : "+l"(accB) : "l"(a.y), "l"(wB[2 * j + 1]));
            }
            float a0, a1, b0, b1;
            asm("mov.b64 {%0, %1}, %2;" : "=f"(a0), "=f"(a1) : "l"(accA));
            asm("mov.b64 {%0, %1}, %2;" : "=f"(b0), "=f"(b1) : "l"(accB));
            const float c0 = a0 + a1;
            const float c1 = b0 + b1;

            float* dst = out + (size_t)orow * C + 2 * chalf;   // 8B aligned
            asm volatile("red.global.add.v2.f32 [%0], {%1, %2};"
                         :: "l"(dst), "f"(c0), "f"(c1) : "memory");
        }
        om_tile += PAIRS_PER_BLOCK;

        // ---- All warps done reading buf before it is refilled at t+2.
        __syncthreads();
    }
}

// ---------------------------------------------------------------------------
// Launch
// ---------------------------------------------------------------------------
extern "C" void kernel_launch(void* const* d_in, const int* in_sizes, int n_in,
                              void* d_out, int out_size)
{
    const float* input   = (const float*)d_in[0];
    const float* kernelw = (const float*)d_in[1];
    const float* bias    = (const float*)d_in[2];
    const int*   in_map  = (const int*)  d_in[3];
    const int*   out_map = (const int*)  d_in[4];
    float*       out     = (float*)d_out;

    const int total4 = N_VOX * (C / 4);
    bias_init_kernel<<<(total4 + 255) / 256, 256>>>(out, bias);

    dim3 grid(M_PAIRS / (PAIRS_PER_BLOCK * TILES), K_OFF);
    scatter_gemm_kernel<<<grid, THREADS>>>(input, kernelw, in_map, out_map, out);
}

// round 15
// speedup vs baseline: 1.0790x; 1.0790x over previous
#include <cuda_runtime.h>
#include <cstdint>

#define N_VOX   262144
#define M_PAIRS 131072
#define K_OFF   27
#define C       32
#define CPAD    36        // row stride in floats (144B; adjacent rows 4 banks apart)

// ---------------------------------------------------------------------------
// Kernel 1: out[n][c] = bias[c]  (bias add commutes with the scatter-adds)
// ---------------------------------------------------------------------------
__global__ void bias_init_kernel(float* __restrict__ out,
                                 const float* __restrict__ bias)
{
    int t = blockIdx.x * blockDim.x + threadIdx.x;
    const int total4 = N_VOX * (C / 4);
    if (t < total4) {
        const float4* b4 = (const float4*)bias;
        float4* o4 = (float4*)out;
        o4[t] = b4[t & 7];
    }
}

// ---------------------------------------------------------------------------
// Kernel 2: per-warp autonomous double-buffered TMA gather pipeline ->
//           input-packed f32x2 GEMM -> red.v2 scatter.
//
//   Each warp owns: 2 x 32-row smem buffers + 2 mbarriers. Per tile of 32
//   pairs: issue gather(t+1) into the idle buffer, wait own mbarrier(t),
//   compute, scatter. NO block-wide sync in steady state -> no convoy
//   stalls (R13/R14 lesson). Weights loaded once per block (amortized
//   over 4 tiles = 128 pairs/warp).
//   Compute (R9/R12, best known): 16-lane half owns one pair; lane covers
//   channels (2c, 2c+1); row read as ulonglong2 (LDS.128 -> packed f32x2
//   input pairs) feeding fma.rn.f32x2 directly.
//   Scatter: red.global.add.v2.f32 (contiguous 128B per pair).
// ---------------------------------------------------------------------------
#define THREADS          128
#define WARPS_PER_BLOCK  4
#define ROWS_PER_TILE    32            // pairs per warp-tile
#define TILES            4             // tiles per warp
#define PAIRS_PER_WARP_T (ROWS_PER_TILE * TILES)            // 128
#define PAIRS_PER_BLOCK  (WARPS_PER_BLOCK * PAIRS_PER_WARP_T) // 512
#define STEPS            16            // 2 pairs per step (one per half-warp)
#define TILE_BYTES       (ROWS_PER_TILE * C * 4)            // 4096

__device__ __forceinline__ uint32_t smem_u32(const void* p) {
    uint32_t a;
    asm("{ .reg .u64 t; cvta.to.shared.u64 t, %1; cvt.u32.u64 %0, t; }"
        : "=r"(a) : "l"(p));
    return a;
}

__device__ __forceinline__ void mbar_wait(uint32_t mbar_a, uint32_t parity) {
    uint32_t done;
    asm volatile(
        "{\n\t"
        ".reg .pred p;\n\t"
        "mbarrier.try_wait.parity.acquire.cta.shared::cta.b64 p, [%1], %2;\n\t"
        "selp.b32 %0, 1, 0, p;\n\t"
        "}"
        : "=r"(done) : "r"(mbar_a), "r"(parity) : "memory");
    if (!done) {
        asm volatile(
            "{\n\t"
            ".reg .pred P1;\n\t"
            "WAIT_LOOP_%=:\n\t"
            "mbarrier.try_wait.parity.acquire.cta.shared::cta.b64 P1, [%0], %1, 0x989680;\n\t"
            "@P1 bra.uni WAIT_DONE_%=;\n\t"
            "bra.uni WAIT_LOOP_%=;\n\t"
            "WAIT_DONE_%=:\n\t"
            "}"
            :: "r"(mbar_a), "r"(parity) : "memory");
    }
}

__device__ __forceinline__ void issue_gather(uint32_t dst, const float* src,
                                             uint32_t mbar_a) {
    asm volatile(
        "cp.async.bulk.shared::cta.global.mbarrier::complete_tx::bytes "
        "[%0], [%1], %2, [%3];"
        :: "r"(dst), "l"(src), "r"(C * 4), "r"(mbar_a) : "memory");
}

__global__ __launch_bounds__(THREADS)
void scatter_gemm_kernel(const float* __restrict__ input,
                         const float* __restrict__ kernel,
                         const int*   __restrict__ in_map,
                         const int*   __restrict__ out_map,
                         float*       __restrict__ out)
{
    __shared__ float srow[WARPS_PER_BLOCK][2][ROWS_PER_TILE][CPAD];  // 36.9 KB
    __shared__ alignas(8) unsigned long long mbar[WARPS_PER_BLOCK][2];

    const int k     = blockIdx.y;
    const int lane  = threadIdx.x & 31;
    const int warp  = threadIdx.x >> 5;
    const int half  = lane >> 4;          // which pair of the step
    const int chalf = lane & 15;          // covers channels 2*chalf, 2*chalf+1

    // Each warp owns a contiguous span of 128 pairs.
    const int wbase = blockIdx.x * PAIRS_PER_BLOCK + warp * PAIRS_PER_WARP_T;
    const int* im   = in_map  + k * M_PAIRS + wbase;
    const int* om   = out_map + k * M_PAIRS + wbase;

    const uint32_t mb0 = smem_u32(&mbar[warp][0]);
    const uint32_t mb1 = smem_u32(&mbar[warp][1]);
    const uint32_t dst0 = smem_u32(&srow[warp][0][lane][0]);
    const uint32_t dst1 = smem_u32(&srow[warp][1][lane][0]);

    if (lane == 0) {
        asm volatile("mbarrier.init.shared.b64 [%0], 1;" :: "r"(mb0) : "memory");
        asm volatile("mbarrier.init.shared.b64 [%0], 1;" :: "r"(mb1) : "memory");
    }
    // One block-wide sync only: make all mbarrier inits visible before any TMA.
    __syncthreads();

    // ---- Prologue: gather tile 0 into buffer 0.
    if (lane == 0)
        asm volatile("mbarrier.arrive.expect_tx.shared.b64 _, [%0], %1;"
                     :: "r"(mb0), "r"(TILE_BYTES) : "memory");
    issue_gather(dst0, input + (size_t)__ldg(im + lane) * C, mb0);

    // ---- Weights (once per block; overlap with tile-0 gather):
    //   wA[i] = (W[2i][c0], W[2i+1][c0]),  wB[i] = (W[2i][c1], W[2i+1][c1])
    const float* Wk = kernel + k * C * C;
    unsigned long long wA[C / 2], wB[C / 2];
    #pragma unroll
    for (int i = 0; i < C / 2; i++) {
        float2 f = __ldg((const float2*)(Wk + (2 * i)     * C) + chalf);
        float2 g = __ldg((const float2*)(Wk + (2 * i + 1) * C) + chalf);
        asm("mov.b64 %0, {%1, %2};" : "=l"(wA[i]) : "f"(f.x), "f"(g.x));
        asm("mov.b64 %0, {%1, %2};" : "=l"(wB[i]) : "f"(f.y), "f"(g.y));
    }

    const float* out_lane = out + 2 * chalf;   // per-lane channel base

    for (int t = 0; t < TILES; t++) {
        const int buf = t & 1;

        // ---- Issue gather for tile t+1 into the other buffer.
        //      Safe by warp program order: that buffer's compute (tile t-1)
        //      already finished in this warp.
        if (t + 1 < TILES) {
            const uint32_t nmb  = (t & 1) ? mb0 : mb1;
            const uint32_t ndst = (t & 1) ? dst0 : dst1;
            if (lane == 0)
                asm volatile("mbarrier.arrive.expect_tx.shared.b64 _, [%0], %1;"
                             :: "r"(nmb), "r"(TILE_BYTES) : "memory");
            issue_gather(ndst,
                         input + (size_t)__ldg(im + (t + 1) * ROWS_PER_TILE + lane) * C,
                         nmb);
        }

        // ---- Wait for tile t (own warp's barrier only — no block convoy).
        mbar_wait(buf ? mb1 : mb0, (t >> 1) & 1);

        // ---- Compute + scatter 32 pairs.
        const int* om_t = om + t * ROWS_PER_TILE;
        #pragma unroll 4
        for (int s = 0; s < STEPS; s++) {
            const int pw   = 2 * s + half;
            const int orow = __ldg(om_t + pw);

            const ulonglong2* r2 = (const ulonglong2*)&srow[warp][buf][pw][0];

            unsigned long long accA = 0ULL, accB = 0ULL;   // packed partials
            #pragma unroll
            for (int j = 0; j < C / 4; j++) {
                ulonglong2 a = r2[j];           // LDS.128, 2 distinct rows/warp
                asm("fma.rn.f32x2 %0, %1, %2, %0;" : "+l"(accA) : "l"(a.x), "l"(wA[2 * j]));
                asm("fma.rn.f32x2 %0, %1, %2, %0;" : "+l"(accA) : "l"(a.y), "l"(wA[2 * j + 1]));
                asm("fma.rn.f32x2 %0, %1, %2, %0;" : "+l"(accB) : "l"(a.x), "l"(wB[2 * j]));
                asm("fma.rn.f32x2 %0, %1, %2, %0;" : "+l"(accB) : "l"(a.y), "l"(wB[2 * j + 1]));
            }
            float a0, a1, b0, b1;
            asm("mov.b64 {%0, %1}, %2;" : "=f"(a0), "=f"(a1) : "l"(accA));
            asm("mov.b64 {%0, %1}, %2;" : "=f"(b0), "=f"(b1) : "l"(accB));
            const float c0 = a0 + a1;
            const float c1 = b0 + b1;

            const float* dst = out_lane + (size_t)orow * C;   // 8B aligned
            asm volatile("red.global.add.v2.f32 [%0], {%1, %2};"
                         :: "l"(dst), "f"(c0), "f"(c1) : "memory");
        }
    }
}

// ---------------------------------------------------------------------------
// Launch
// ---------------------------------------------------------------------------
extern "C" void kernel_launch(void* const* d_in, const int* in_sizes, int n_in,
                              void* d_out, int out_size)
{
    const float* input   = (const float*)d_in[0];
    const float* kernelw = (const float*)d_in[1];
    const float* bias    = (const float*)d_in[2];
    const int*   in_map  = (const int*)  d_in[3];
    const int*   out_map = (const int*)  d_in[4];
    float*       out     = (float*)d_out;

    const int total4 = N_VOX * (C / 4);
    bias_init_kernel<<<(total4 + 255) / 256, 256>>>(out, bias);

    dim3 grid(M_PAIRS / PAIRS_PER_BLOCK, K_OFF);
    scatter_gemm_kernel<<<grid, THREADS>>>(input, kernelw, in_map, out_map, out);
}

// round 17
// speedup vs baseline: 1.2689x; 1.1759x over previous
#include <cuda_runtime.h>
#include <cstdint>

#define N_VOX   262144
#define M_PAIRS 131072
#define K_OFF   27
#define C       32
#define CPAD    36        // srow stride (floats): bank = (4*row+col)%32, conflict-free frags
#define BPAD    40        // weight tile stride (floats): bank = (8*k+n)%32, conflict-free

#define THREADS          128
#define WARPS_PER_BLOCK  4
#define PAIRS_PER_BLOCK  128
#define PAIRS_PER_WARP   32

// ---------------------------------------------------------------------------
// Kernel 1: out[n][c] = bias[c]  (bias add commutes with the scatter-adds)
// ---------------------------------------------------------------------------
__global__ void bias_init_kernel(float* __restrict__ out,
                                 const float* __restrict__ bias)
{
    int t = blockIdx.x * blockDim.x + threadIdx.x;
    const int total4 = N_VOX * (C / 4);
    if (t < total4) {
        const float4* b4 = (const float4*)bias;
        float4* o4 = (float4*)out;
        o4[t] = b4[t & 7];
    }
}

// ---------------------------------------------------------------------------
// Helpers
// ---------------------------------------------------------------------------
__device__ __forceinline__ uint32_t smem_u32(const void* p) {
    uint32_t a;
    asm("{ .reg .u64 t; cvta.to.shared.u64 t, %1; cvt.u32.u64 %0, t; }"
        : "=r"(a) : "l"(p));
    return a;
}

__device__ __forceinline__ uint32_t tf32_bits(float x) {
    uint32_t b;
    asm("cvt.rna.tf32.f32 %0, %1;" : "=r"(b) : "f"(x));
    return b;
}

__device__ __forceinline__ void mbar_wait(uint32_t mbar_a, uint32_t parity) {
    uint32_t done;
    asm volatile(
        "{\n\t"
        ".reg .pred p;\n\t"
        "mbarrier.try_wait.parity.acquire.cta.shared::cta.b64 p, [%1], %2;\n\t"
        "selp.b32 %0, 1, 0, p;\n\t"
        "}"
        : "=r"(done) : "r"(mbar_a), "r"(parity) : "memory");
    if (!done) {
        asm volatile(
            "{\n\t"
            ".reg .pred P1;\n\t"
            "WAIT_LOOP_%=:\n\t"
            "mbarrier.try_wait.parity.acquire.cta.shared::cta.b64 P1, [%0], %1, 0x989680;\n\t"
            "@P1 bra.uni WAIT_DONE_%=;\n\t"
            "bra.uni WAIT_LOOP_%=;\n\t"
            "WAIT_DONE_%=:\n\t"
            "}"
            :: "r"(mbar_a), "r"(parity) : "memory");
    }
}

// mma.sync m16n8k8 tf32: D += A*B (fp32 accumulate), baseline PTX (sm_80+).
__device__ __forceinline__ void mma_tf32(float* c,
                                         uint32_t a0, uint32_t a1, uint32_t a2, uint32_t a3,
                                         uint32_t b0, uint32_t b1) {
    asm volatile(
        "mma.sync.aligned.m16n8k8.row.col.f32.tf32.tf32.f32 "
        "{%0,%1,%2,%3}, {%4,%5,%6,%7}, {%8,%9}, {%0,%1,%2,%3};"
        : "+f"(c[0]), "+f"(c[1]), "+f"(c[2]), "+f"(c[3])
        : "r"(a0), "r"(a1), "r"(a2), "r"(a3), "r"(b0), "r"(b1));
}

// ---------------------------------------------------------------------------
// Kernel 2: TMA gather -> smem -> tf32 mma.sync (3-term) -> red.v2 scatter.
//
//   Per warp: 32 pairs = 2 m16 tiles x 4 n8 tiles x 4 k8 steps, 3 terms
//   (hi*wh + hi*wl + lo*wh) = 96 mma.sync. A fragments read from staged
//   rows (on-the-fly tf32 hi/lo split); B fragments from per-block tf32
//   weight tiles in smem. D fragment (c0,c1 = adjacent channels) scatters
//   directly via red.global.add.v2.f32.
// ---------------------------------------------------------------------------
__global__ __launch_bounds__(THREADS)
void mma_scatter_kernel(const float* __restrict__ input,
                        const float* __restrict__ kernelw,
                        const int*   __restrict__ in_map,
                        const int*   __restrict__ out_map,
                        float*       __restrict__ out)
{
    __shared__ float srow[PAIRS_PER_BLOCK][CPAD];    // 18 KB staged rows
    __shared__ float sBh[C][BPAD];                   // 5 KB tf32-hi weights [k][n]
    __shared__ float sBl[C][BPAD];                   // 5 KB tf32-lo weights
    __shared__ alignas(8) unsigned long long mbar;

    const int k    = blockIdx.y;
    const int tid  = threadIdx.x;
    const int lane = tid & 31;
    const int warp = tid >> 5;
    const int gid  = lane >> 2;           // fragment row group (0..7)
    const int quad = lane & 3;            // fragment col group (0..3)

    const int base0 = blockIdx.x * PAIRS_PER_BLOCK;
    const int* im = in_map  + k * M_PAIRS + base0;
    const int* om = out_map + k * M_PAIRS + base0;

    const uint32_t mb = smem_u32(&mbar);

    if (tid == 0) {
        asm volatile("mbarrier.init.shared.b64 [%0], 1;" :: "r"(mb) : "memory");
        asm volatile("mbarrier.arrive.expect_tx.shared.b64 _, [%0], %1;"
                     :: "r"(mb), "r"(PAIRS_PER_BLOCK * C * 4) : "memory");
    }
    __syncthreads();

    // ---- Gather: one 128B bulk copy per thread (row -> padded smem slot).
    {
        const int irow = __ldg(im + tid);
        asm volatile(
            "cp.async.bulk.shared::cta.global.mbarrier::complete_tx::bytes "
            "[%0], [%1], %2, [%3];"
            :: "r"(smem_u32(&srow[tid][0])), "l"(input + (size_t)irow * C),
               "r"(C * 4), "r"(mb) : "memory");
    }

    // ---- Weights: tf32 hi/lo split into smem, B[k_in][n] (overlaps gather).
    {
        const float* Wk = kernelw + k * C * C;
        #pragma unroll
        for (int idx = tid; idx < C * C; idx += THREADS) {
            const int ki = idx >> 5;
            const int n  = idx & 31;
            const float w  = __ldg(Wk + idx);          // kernel[k][ki][n]
            const uint32_t whb = tf32_bits(w);
            const float wh = __uint_as_float(whb);
            sBh[ki][n] = wh;
            sBl[ki][n] = __uint_as_float(tf32_bits(w - wh));
        }
    }
    __syncthreads();          // weights visible to all warps
    mbar_wait(mb, 0);         // staged rows visible (acquire)

    // ---- Compute: warp owns pairs [warp*32, warp*32+32).
    const int pbase = warp * PAIRS_PER_WARP;

    float acc[2][4][4];       // [mtile][ntile][frag]
    #pragma unroll
    for (int mt = 0; mt < 2; mt++)
        #pragma unroll
        for (int nt = 0; nt < 4; nt++)
            #pragma unroll
            for (int i = 0; i < 4; i++) acc[mt][nt][i] = 0.f;

    #pragma unroll
    for (int ks = 0; ks < 4; ks++) {
        const int col = ks * 8 + quad;

        // A fragments (both m-tiles), on-the-fly hi/lo split.
        uint32_t ah[2][4], al[2][4];
        #pragma unroll
        for (int mt = 0; mt < 2; mt++) {
            const int r0 = pbase + mt * 16 + gid;
            const float x0 = srow[r0][col];
            const float x1 = srow[r0 + 8][col];
            const float x2 = srow[r0][col + 4];
            const float x3 = srow[r0 + 8][col + 4];
            ah[mt][0] = tf32_bits(x0);
            ah[mt][1] = tf32_bits(x1);
            ah[mt][2] = tf32_bits(x2);
            ah[mt][3] = tf32_bits(x3);
            al[mt][0] = tf32_bits(x0 - __uint_as_float(ah[mt][0]));
            al[mt][1] = tf32_bits(x1 - __uint_as_float(ah[mt][1]));
            al[mt][2] = tf32_bits(x2 - __uint_as_float(ah[mt][2]));
            al[mt][3] = tf32_bits(x3 - __uint_as_float(ah[mt][3]));
        }

        #pragma unroll
        for (int nt = 0; nt < 4; nt++) {
            const int n = nt * 8 + gid;
            const uint32_t bh0 = __float_as_uint(sBh[ks * 8 + quad][n]);
            const uint32_t bh1 = __float_as_uint(sBh[ks * 8 + quad + 4][n]);
            const uint32_t bl0 = __float_as_uint(sBl[ks * 8 + quad][n]);
            const uint32_t bl1 = __float_as_uint(sBl[ks * 8 + quad + 4][n]);

            #pragma unroll
            for (int mt = 0; mt < 2; mt++) {
                mma_tf32(acc[mt][nt], ah[mt][0], ah[mt][1], ah[mt][2], ah[mt][3], bh0, bh1);
                mma_tf32(acc[mt][nt], ah[mt][0], ah[mt][1], ah[mt][2], ah[mt][3], bl0, bl1);
                mma_tf32(acc[mt][nt], al[mt][0], al[mt][1], al[mt][2], al[mt][3], bh0, bh1);
            }
        }
    }

    // ---- Scatter: D frag rows = pairs; (c0,c1) and (c2,c3) are adjacent
    //      channels -> red.v2 each. 8B-aligned (col = nt*8 + 2*quad).
    #pragma unroll
    for (int mt = 0; mt < 2; mt++) {
        const int orow0 = __ldg(om + pbase + mt * 16 + gid);
        const int orow1 = __ldg(om + pbase + mt * 16 + gid + 8);
        float* d0 = out + (size_t)orow0 * C + 2 * quad;
        float* d1 = out + (size_t)orow1 * C + 2 * quad;
        #pragma unroll
        for (int nt = 0; nt < 4; nt++) {
            asm volatile("red.global.add.v2.f32 [%0], {%1, %2};"
                         :: "l"(d0 + nt * 8), "f"(acc[mt][nt][0]), "f"(acc[mt][nt][1])
                         : "memory");
            asm volatile("red.global.add.v2.f32 [%0], {%1, %2};"
                         :: "l"(d1 + nt * 8), "f"(acc[mt][nt][2]), "f"(acc[mt][nt][3])
                         : "memory");
        }
    }
}

// ---------------------------------------------------------------------------
// Launch
// ---------------------------------------------------------------------------
extern "C" void kernel_launch(void* const* d_in, const int* in_sizes, int n_in,
                              void* d_out, int out_size)
{
    const float* input   = (const float*)d_in[0];
    const float* kernelw = (const float*)d_in[1];
    const float* bias    = (const float*)d_in[2];
    const int*   in_map  = (const int*)  d_in[3];
    const int*   out_map = (const int*)  d_in[4];
    float*       out     = (float*)d_out;

    const int total4 = N_VOX * (C / 4);
    bias_init_kernel<<<(total4 + 255) / 256, 256>>>(out, bias);

    dim3 grid(M_PAIRS / PAIRS_PER_BLOCK, K_OFF);
    mma_scatter_kernel<<<grid, THREADS>>>(input, kernelw, in_map, out_map, out);
}